// round 3
// baseline (speedup 1.0000x reference)
#include <cuda_runtime.h>
#include <cuda_bf16.h>
#include <cstdint>
#include <math.h>

#define B_WIN   3136
#define NTOK    64
#define DIM     256
#define HEADS   8
#define NW      49
#define LBIAS   225
#define ATT_SCALE 0.17677669529663687f  // 1/sqrt(32)

// Scratch (device globals; alloc APIs forbidden)
// sizes: q/k/v = B_*H*64*32 = 51,380,224 ; ot = B_*64*256 = 51,380,224
__device__ float g_q [51380224];   // [B_*H][64][32]
__device__ float g_k [51380224];
__device__ float g_v [51380224];
__device__ float g_ot[51380224];   // [B_*64][256] context
__device__ float g_ptab[LBIAS * HEADS];

// ---------------------------------------------------------------------------
__device__ __forceinline__ void split2(float x, float y, uint32_t& hi, uint32_t& lo) {
    __nv_bfloat162 h = __floats2bfloat162_rn(x, y);
    float hx = __low2float(h), hy = __high2float(h);
    __nv_bfloat162 l = __floats2bfloat162_rn(x - hx, y - hy);
    hi = *reinterpret_cast<uint32_t*>(&h);
    lo = *reinterpret_cast<uint32_t*>(&l);
}

__device__ __forceinline__ void mma_bf16(float* c, const uint32_t* a, uint32_t b0, uint32_t b1) {
    asm volatile(
        "mma.sync.aligned.m16n8k16.row.col.f32.bf16.bf16.f32 "
        "{%0,%1,%2,%3}, {%4,%5,%6,%7}, {%8,%9}, {%0,%1,%2,%3};\n"
        : "+f"(c[0]), "+f"(c[1]), "+f"(c[2]), "+f"(c[3])
        : "r"(a[0]), "r"(a[1]), "r"(a[2]), "r"(a[3]), "r"(b0), "r"(b1));
}

// ---------------------------------------------------------------------------
// Kernel 1: DynamicPosBias MLP -> g_ptab[225][8]  (fp32 exact)
// ---------------------------------------------------------------------------
__device__ __forceinline__ void lnrelu16(const float* p, float* t,
                                         const float* gm, const float* bt) {
    float m = 0.f;
#pragma unroll
    for (int j = 0; j < 16; j++) m += p[j];
    m *= (1.f / 16.f);
    float v = 0.f;
#pragma unroll
    for (int j = 0; j < 16; j++) { float d = p[j] - m; v += d * d; }
    v *= (1.f / 16.f);
    float is = rsqrtf(v + 1e-5f);
#pragma unroll
    for (int j = 0; j < 16; j++) {
        float u = (p[j] - m) * is * gm[j] + bt[j];
        t[j] = u > 0.f ? u : 0.f;
    }
}

__global__ void dpb_kernel(const float* __restrict__ biases,
                           const float* __restrict__ pw, const float* __restrict__ pb,
                           const float* __restrict__ g1, const float* __restrict__ b1,
                           const float* __restrict__ w1, const float* __restrict__ c1,
                           const float* __restrict__ g2, const float* __restrict__ b2,
                           const float* __restrict__ w2, const float* __restrict__ c2,
                           const float* __restrict__ g3, const float* __restrict__ b3,
                           const float* __restrict__ w3, const float* __restrict__ c3) {
    int r = threadIdx.x;
    if (r >= LBIAS) return;
    float p[16], t[16];
    float x0 = biases[2 * r], x1 = biases[2 * r + 1];
#pragma unroll
    for (int j = 0; j < 16; j++) p[j] = x0 * pw[2 * j] + x1 * pw[2 * j + 1] + pb[j];
    lnrelu16(p, t, g1, b1);
#pragma unroll
    for (int o = 0; o < 16; o++) {
        float s = c1[o];
#pragma unroll
        for (int j = 0; j < 16; j++) s += t[j] * w1[o * 16 + j];
        p[o] = s;
    }
    lnrelu16(p, t, g2, b2);
#pragma unroll
    for (int o = 0; o < 16; o++) {
        float s = c2[o];
#pragma unroll
        for (int j = 0; j < 16; j++) s += t[j] * w2[o * 16 + j];
        p[o] = s;
    }
    lnrelu16(p, t, g3, b3);
#pragma unroll
    for (int o = 0; o < 8; o++) {
        float s = c3[o];
#pragma unroll
        for (int j = 0; j < 16; j++) s += t[j] * w3[o * 16 + j];
        g_ptab[r * 8 + o] = s;
    }
}

// ---------------------------------------------------------------------------
// Kernel 2/4: Y[M,NO] = A[M,256] @ W[NO,256]^T + bias ; BM=BN=128, BK=32.
// MODE 0: qkv -> scatter to g_q(*scale)/g_k/g_v ; MODE 1: proj -> Out.
// ---------------------------------------------------------------------------
template <int MODE>
__global__ __launch_bounds__(256, 2) void gemm_kernel(const float* __restrict__ Ain,
                                                      const float* __restrict__ W,
                                                      const float* __restrict__ bias,
                                                      float* __restrict__ Out) {
    __shared__ uint32_t Ah[128][17], Al[128][17], Bh[128][17], Bl[128][17];
    const float* A = (MODE == 0) ? Ain : g_ot;
    int bm = blockIdx.y, bn = blockIdx.x;
    int tid = threadIdx.x;
    int warp = tid >> 5, lane = tid & 31;
    int wm = warp >> 1, wn = warp & 1;
    int g = lane >> 2, tg = lane & 3;

    float acc[2][8][4];
#pragma unroll
    for (int a = 0; a < 2; a++)
#pragma unroll
        for (int b = 0; b < 8; b++)
#pragma unroll
            for (int c = 0; c < 4; c++) acc[a][b][c] = 0.f;

    const float* Ab = A + (size_t)bm * 128 * 256;
    const float* Wb = W + (size_t)bn * 128 * 256;
    int r0 = tid >> 3;
    int cc = (tid & 7) * 4;

    for (int kb = 0; kb < 8; kb++) {
        __syncthreads();
#pragma unroll
        for (int i = 0; i < 4; i++) {
            int r = r0 + i * 32;
            float4 av = *(const float4*)(Ab + (size_t)r * 256 + kb * 32 + cc);
            float4 bv = *(const float4*)(Wb + (size_t)r * 256 + kb * 32 + cc);
            int j = cc >> 1;
            split2(av.x, av.y, Ah[r][j], Al[r][j]);
            split2(av.z, av.w, Ah[r][j + 1], Al[r][j + 1]);
            split2(bv.x, bv.y, Bh[r][j], Bl[r][j]);
            split2(bv.z, bv.w, Bh[r][j + 1], Bl[r][j + 1]);
        }
        __syncthreads();
#pragma unroll
        for (int ks = 0; ks < 2; ks++) {
            int j0 = ks * 8;
            uint32_t ah[2][4], al[2][4];
#pragma unroll
            for (int mf = 0; mf < 2; mf++) {
                int mr = wm * 32 + mf * 16;
                ah[mf][0] = Ah[mr + g][j0 + tg];         al[mf][0] = Al[mr + g][j0 + tg];
                ah[mf][1] = Ah[mr + g + 8][j0 + tg];     al[mf][1] = Al[mr + g + 8][j0 + tg];
                ah[mf][2] = Ah[mr + g][j0 + tg + 4];     al[mf][2] = Al[mr + g][j0 + tg + 4];
                ah[mf][3] = Ah[mr + g + 8][j0 + tg + 4]; al[mf][3] = Al[mr + g + 8][j0 + tg + 4];
            }
#pragma unroll
            for (int nf = 0; nf < 8; nf++) {
                int nr = wn * 64 + nf * 8 + g;
                uint32_t bh0 = Bh[nr][j0 + tg], bh1 = Bh[nr][j0 + tg + 4];
                uint32_t bl0 = Bl[nr][j0 + tg], bl1 = Bl[nr][j0 + tg + 4];
#pragma unroll
                for (int mf = 0; mf < 2; mf++) {
                    mma_bf16(acc[mf][nf], ah[mf], bh0, bh1);
                    mma_bf16(acc[mf][nf], ah[mf], bl0, bl1);
                    mma_bf16(acc[mf][nf], al[mf], bh0, bh1);
                }
            }
        }
    }

    int obase = bn * 128 + wn * 64;
#pragma unroll
    for (int nf = 0; nf < 8; nf++) {
        int o = obase + nf * 8 + 2 * tg;
        float bb0 = bias[o], bb1 = bias[o + 1];
#pragma unroll
        for (int mf = 0; mf < 2; mf++) {
#pragma unroll
            for (int r2 = 0; r2 < 2; r2++) {
                int m = bm * 128 + wm * 32 + mf * 16 + g + r2 * 8;
                float v0 = acc[mf][nf][r2 * 2] + bb0;
                float v1 = acc[mf][nf][r2 * 2 + 1] + bb1;
                if (MODE == 1) {
                    *(float2*)(Out + (size_t)m * 256 + o) = make_float2(v0, v1);
                } else {
                    int s = o >> 8, hh = (o >> 5) & 7, d = o & 31;
                    int bw = m >> 6, n = m & 63;
                    size_t di = ((size_t)(bw * 8 + hh) * 64 + n) * 32 + d;
                    float* dst = (s == 0) ? g_q : (s == 1) ? g_k : g_v;
                    if (s == 0) { v0 *= ATT_SCALE; v1 *= ATT_SCALE; }
                    *(float2*)(dst + di) = make_float2(v0, v1);
                }
            }
        }
    }
}

// ---------------------------------------------------------------------------
// Kernel 3: attention per (window b, head h). 4 warps, 16 query rows each.
// ---------------------------------------------------------------------------
__global__ __launch_bounds__(128) void attn_kernel(const float* __restrict__ mask,
                                                   const int* __restrict__ rel_idx) {
    __shared__ uint32_t qh[64][17], ql[64][17], kh[64][17], kl[64][17];
    __shared__ uint32_t vth[32][33], vtl[32][33];   // V^T: [d][token-pair]
    __shared__ uint32_t ph[64][33], pl[64][33];     // probs

    int b = blockIdx.x, h = blockIdx.y;
    int tid = threadIdx.x;
    int warp = tid >> 5, lane = tid & 31;
    int g = lane >> 2, tg = lane & 3;

    const float* qg = g_q + (size_t)(b * 8 + h) * 2048;
    const float* kg = g_k + (size_t)(b * 8 + h) * 2048;
    const float* vg = g_v + (size_t)(b * 8 + h) * 2048;

    for (int it = tid; it < 1024; it += 128) {
        int j = it & 15, t = it >> 4;
        float2 a = *(const float2*)(qg + t * 32 + 2 * j);
        split2(a.x, a.y, qh[t][j], ql[t][j]);
        float2 c = *(const float2*)(kg + t * 32 + 2 * j);
        split2(c.x, c.y, kh[t][j], kl[t][j]);
    }
    for (int it = tid; it < 1024; it += 128) {
        int d = it & 31, j = it >> 5;
        split2(vg[(2 * j) * 32 + d], vg[(2 * j + 1) * 32 + d], vth[d][j], vtl[d][j]);
    }
    __syncthreads();

    // logits = q @ k^T  (q pre-scaled)
    float acc[8][4];
#pragma unroll
    for (int a = 0; a < 8; a++)
#pragma unroll
        for (int c = 0; c < 4; c++) acc[a][c] = 0.f;

    int mr = warp * 16;
#pragma unroll
    for (int ks = 0; ks < 2; ks++) {
        int j0 = ks * 8;
        uint32_t ah[4], al[4];
        ah[0] = qh[mr + g][j0 + tg];         al[0] = ql[mr + g][j0 + tg];
        ah[1] = qh[mr + g + 8][j0 + tg];     al[1] = ql[mr + g + 8][j0 + tg];
        ah[2] = qh[mr + g][j0 + tg + 4];     al[2] = ql[mr + g][j0 + tg + 4];
        ah[3] = qh[mr + g + 8][j0 + tg + 4]; al[3] = ql[mr + g + 8][j0 + tg + 4];
#pragma unroll
        for (int nf = 0; nf < 8; nf++) {
            int nr = nf * 8 + g;
            uint32_t bh0 = kh[nr][j0 + tg], bh1 = kh[nr][j0 + tg + 4];
            uint32_t bl0 = kl[nr][j0 + tg], bl1 = kl[nr][j0 + tg + 4];
            mma_bf16(acc[nf], ah, bh0, bh1);
            mma_bf16(acc[nf], ah, bl0, bl1);
            mma_bf16(acc[nf], al, bh0, bh1);
        }
    }

    // bias gather + mask
    int wb = b % NW;
    const float* mrow = mask + (size_t)wb * 4096;
    int r0 = mr + g, r1 = r0 + 8;
#pragma unroll
    for (int nf = 0; nf < 8; nf++) {
        int n0 = nf * 8 + 2 * tg;
        acc[nf][0] += g_ptab[rel_idx[r0 * 64 + n0] * 8 + h]     + mrow[r0 * 64 + n0];
        acc[nf][1] += g_ptab[rel_idx[r0 * 64 + n0 + 1] * 8 + h] + mrow[r0 * 64 + n0 + 1];
        acc[nf][2] += g_ptab[rel_idx[r1 * 64 + n0] * 8 + h]     + mrow[r1 * 64 + n0];
        acc[nf][3] += g_ptab[rel_idx[r1 * 64 + n0 + 1] * 8 + h] + mrow[r1 * 64 + n0 + 1];
    }

    // softmax across the quad (rows r0, r1)
    float m0 = -1e30f, m1 = -1e30f;
#pragma unroll
    for (int nf = 0; nf < 8; nf++) {
        m0 = fmaxf(m0, fmaxf(acc[nf][0], acc[nf][1]));
        m1 = fmaxf(m1, fmaxf(acc[nf][2], acc[nf][3]));
    }
    m0 = fmaxf(m0, __shfl_xor_sync(0xffffffffu, m0, 1));
    m0 = fmaxf(m0, __shfl_xor_sync(0xffffffffu, m0, 2));
    m1 = fmaxf(m1, __shfl_xor_sync(0xffffffffu, m1, 1));
    m1 = fmaxf(m1, __shfl_xor_sync(0xffffffffu, m1, 2));

    float s0 = 0.f, s1 = 0.f;
#pragma unroll
    for (int nf = 0; nf < 8; nf++) {
        acc[nf][0] = __expf(acc[nf][0] - m0); s0 += acc[nf][0];
        acc[nf][1] = __expf(acc[nf][1] - m0); s0 += acc[nf][1];
        acc[nf][2] = __expf(acc[nf][2] - m1); s1 += acc[nf][2];
        acc[nf][3] = __expf(acc[nf][3] - m1); s1 += acc[nf][3];
    }
    s0 += __shfl_xor_sync(0xffffffffu, s0, 1);
    s0 += __shfl_xor_sync(0xffffffffu, s0, 2);
    s1 += __shfl_xor_sync(0xffffffffu, s1, 1);
    s1 += __shfl_xor_sync(0xffffffffu, s1, 2);
    float i0 = 1.f / s0, i1 = 1.f / s1;

#pragma unroll
    for (int nf = 0; nf < 8; nf++) {
        split2(acc[nf][0] * i0, acc[nf][1] * i0, ph[r0][nf * 4 + tg], pl[r0][nf * 4 + tg]);
        split2(acc[nf][2] * i1, acc[nf][3] * i1, ph[r1][nf * 4 + tg], pl[r1][nf * 4 + tg]);
    }
    __syncwarp();

    // out = P @ V
    float oacc[4][4];
#pragma unroll
    for (int a = 0; a < 4; a++)
#pragma unroll
        for (int c = 0; c < 4; c++) oacc[a][c] = 0.f;

#pragma unroll
    for (int ks = 0; ks < 4; ks++) {
        int j0 = ks * 8;
        uint32_t ah[4], al[4];
        ah[0] = ph[mr + g][j0 + tg];         al[0] = pl[mr + g][j0 + tg];
        ah[1] = ph[mr + g + 8][j0 + tg];     al[1] = pl[mr + g + 8][j0 + tg];
        ah[2] = ph[mr + g][j0 + tg + 4];     al[2] = pl[mr + g][j0 + tg + 4];
        ah[3] = ph[mr + g + 8][j0 + tg + 4]; al[3] = pl[mr + g + 8][j0 + tg + 4];
#pragma unroll
        for (int nf = 0; nf < 4; nf++) {
            int nr = nf * 8 + g;  // d column
            uint32_t bh0 = vth[nr][j0 + tg], bh1 = vth[nr][j0 + tg + 4];
            uint32_t bl0 = vtl[nr][j0 + tg], bl1 = vtl[nr][j0 + tg + 4];
            mma_bf16(oacc[nf], ah, bh0, bh1);
            mma_bf16(oacc[nf], ah, bl0, bl1);
            mma_bf16(oacc[nf], al, bh0, bh1);
        }
    }

    // ctx -> g_ot[(b*64+n)*256 + h*32 + d]
#pragma unroll
    for (int nf = 0; nf < 4; nf++) {
        int d0 = nf * 8 + 2 * tg;
        *(float2*)(g_ot + ((size_t)(b * 64 + r0)) * 256 + h * 32 + d0) =
            make_float2(oacc[nf][0], oacc[nf][1]);
        *(float2*)(g_ot + ((size_t)(b * 64 + r1)) * 256 + h * 32 + d0) =
            make_float2(oacc[nf][2], oacc[nf][3]);
    }
}

// ---------------------------------------------------------------------------
extern "C" void kernel_launch(void* const* d_in, const int* in_sizes, int n_in,
                              void* d_out, int out_size) {
    (void)in_sizes; (void)n_in; (void)out_size;
    const float* x       = (const float*)d_in[0];
    const float* mask    = (const float*)d_in[1];
    const float* qkv_w   = (const float*)d_in[2];
    const float* qkv_b   = (const float*)d_in[3];
    const float* proj_w  = (const float*)d_in[4];
    const float* proj_b  = (const float*)d_in[5];
    const float* pposw   = (const float*)d_in[6];
    const float* pposb   = (const float*)d_in[7];
    const float* ln1g    = (const float*)d_in[8];
    const float* ln1b    = (const float*)d_in[9];
    const float* fc1w    = (const float*)d_in[10];
    const float* fc1b    = (const float*)d_in[11];
    const float* ln2g    = (const float*)d_in[12];
    const float* ln2b    = (const float*)d_in[13];
    const float* fc2w    = (const float*)d_in[14];
    const float* fc2b    = (const float*)d_in[15];
    const float* ln3g    = (const float*)d_in[16];
    const float* ln3b    = (const float*)d_in[17];
    const float* fc3w    = (const float*)d_in[18];
    const float* fc3b    = (const float*)d_in[19];
    const float* biases  = (const float*)d_in[20];
    const int*   rel_idx = (const int*)d_in[21];
    float* out = (float*)d_out;

    dpb_kernel<<<1, 256>>>(biases, pposw, pposb, ln1g, ln1b, fc1w, fc1b,
                           ln2g, ln2b, fc2w, fc2b, ln3g, ln3b, fc3w, fc3b);
    gemm_kernel<0><<<dim3(6, 1568), 256>>>(x, qkv_w, qkv_b, nullptr);
    attn_kernel<<<dim3(B_WIN, HEADS), 128>>>(mask, rel_idx);
    gemm_kernel<1><<<dim3(2, 1568), 256>>>(nullptr, proj_w, proj_b, out);
}